// round 2
// baseline (speedup 1.0000x reference)
#include <cuda_runtime.h>

#define N_NODES 4096
#define E_EDGES 16384
#define HID 128

typedef unsigned long long ull;

// ---------------- scratch (device globals; no allocations allowed) ----------------
__device__ __align__(16) float g_h1[N_NODES * HID];
__device__ __align__(16) float g_h2[N_NODES * HID];
__device__ __align__(16) float g_agg[N_NODES * HID];
__device__ __align__(16) float g_agg3[N_NODES * 2];
__device__ float g_cnt[N_NODES];

// ---------------- packed fp32x2 helpers (Blackwell sm_100+) ----------------
__device__ __forceinline__ ull pk2(float lo, float hi) {
    ull r; asm("mov.b64 %0, {%1, %2};" : "=l"(r) : "f"(lo), "f"(hi)); return r;
}
__device__ __forceinline__ void upk2(ull v, float &lo, float &hi) {
    asm("mov.b64 {%0, %1}, %2;" : "=f"(lo), "=f"(hi) : "l"(v));
}
__device__ __forceinline__ ull ffma2(ull a, ull b, ull c) {
    ull r; asm("fma.rn.f32x2 %0, %1, %2, %3;" : "=l"(r) : "l"(a), "l"(b), "l"(c)); return r;
}
__device__ __forceinline__ ull relu2(ull v) {
    float lo, hi; upk2(v, lo, hi);
    return pk2(fmaxf(lo, 0.f), fmaxf(hi, 0.f));
}

// ---------------- init: zero accumulators + counts ----------------
__global__ void k_init() {
    int t = blockIdx.x * blockDim.x + threadIdx.x;
    int stride = gridDim.x * blockDim.x;
    for (int i = t; i < N_NODES * HID; i += stride) g_agg[i] = 0.f;
    for (int i = t; i < N_NODES * 2; i += stride) g_agg3[i] = 0.f;
    for (int i = t; i < N_NODES; i += stride) g_cnt[i] = 0.f;
}

// ---------------- in-degree counts ----------------
__global__ void k_cnt(const int* __restrict__ dst) {
    int e = blockIdx.x * blockDim.x + threadIdx.x;
    if (e < E_EDGES) atomicAdd(&g_cnt[dst[e]], 1.f);
}

// ---------------- layer 1 edge: IN=4 -> 128, tiny ----------------
__global__ void k_l1_edge(const float* __restrict__ x, const float* __restrict__ ea,
                          const int* __restrict__ src, const int* __restrict__ dst,
                          const float* __restrict__ w1, const float* __restrict__ b1) {
    int t = blockIdx.x * blockDim.x + threadIdx.x;   // E*128 threads
    int e = t >> 7;
    int o = t & 127;
    float a0 = __ldg(&ea[2 * e]);
    float a1 = __ldg(&ea[2 * e + 1]);
    int s = __ldg(&src[e]);
    float4 xs = __ldg((const float4*)(x + 4 * s));
    float xv[4] = {xs.x, xs.y, xs.z, xs.w};
    float acc = 0.f;
#pragma unroll
    for (int i = 0; i < 4; i++) {
        int idx = i * 128 + o;
        float z = fmaf(a1, __ldg(&w1[512 + idx]), fmaf(a0, __ldg(&w1[idx]), __ldg(&b1[idx])));
        acc = fmaf(xv[i], fmaxf(z, 0.f), acc);
    }
    atomicAdd(&g_agg[__ldg(&dst[e]) * 128 + o], acc);
}

// ---------------- layer 1 node: h1 = relu(agg/cnt + x@r1 + c1); re-zero agg ----------------
__global__ void k_l1_node(const float* __restrict__ x, const float* __restrict__ r1,
                          const float* __restrict__ c1) {
    int t = blockIdx.x * blockDim.x + threadIdx.x;   // N*128 threads
    int n = t >> 7;
    int o = t & 127;
    float inv = 1.f / fmaxf(g_cnt[n], 1.f);
    float4 xs = __ldg((const float4*)(x + 4 * n));
    float root = 0.f;
    root = fmaf(xs.x, __ldg(&r1[0 * 128 + o]), root);
    root = fmaf(xs.y, __ldg(&r1[1 * 128 + o]), root);
    root = fmaf(xs.z, __ldg(&r1[2 * 128 + o]), root);
    root = fmaf(xs.w, __ldg(&r1[3 * 128 + o]), root);
    float v = fmaf(g_agg[t], inv, root + __ldg(&c1[o]));
    g_h1[t] = fmaxf(v, 0.f);
    g_agg[t] = 0.f;   // ready for layer 2
}

// ---------------- layer 2 edge: THE hot kernel ----------------
// warp = 8 edges; lane = 4 consecutive output channels (2 f32x2 pairs).
// W0/W1/b2 (192 KB) stay L1-resident; each W load is reused by 8 edges in regs.
__global__ void __launch_bounds__(256) k_l2_edge(
        const float* __restrict__ h1, const float* __restrict__ ea,
        const int* __restrict__ src, const int* __restrict__ dst,
        const float* __restrict__ w2, const float* __restrict__ b2,
        float* __restrict__ agg) {
    const int lane = threadIdx.x & 31;
    const int warp = threadIdx.x >> 5;
    const int ebase = (blockIdx.x * 8 + warp) * 8;   // 256 blocks * 8 warps * 8 edges = 16384
    const int o4 = lane << 2;

    const float* W0 = w2;
    const float* W1 = w2 + 16384;

    ull ea0p[8], ea1p[8];
    int sidx[8], didx[8];
#pragma unroll
    for (int e = 0; e < 8; e++) {
        int ei = ebase + e;
        float a0 = __ldg(&ea[2 * ei]);
        float a1 = __ldg(&ea[2 * ei + 1]);
        ea0p[e] = pk2(a0, a0);
        ea1p[e] = pk2(a1, a1);
        sidx[e] = __ldg(&src[ei]) * 128;
        didx[e] = __ldg(&dst[ei]) * 128;
    }

    ull acc0[8], acc1[8];
#pragma unroll
    for (int e = 0; e < 8; e++) { acc0[e] = 0ull; acc1[e] = 0ull; }

    for (int i4 = 0; i4 < 128; i4 += 4) {
        float4 h4[8];
#pragma unroll
        for (int e = 0; e < 8; e++)
            h4[e] = __ldg((const float4*)(h1 + sidx[e] + i4));
#pragma unroll
        for (int ii = 0; ii < 4; ii++) {
            int idx = (i4 + ii) * 128 + o4;
            float4 w0v = __ldg((const float4*)(W0 + idx));
            float4 w1v = __ldg((const float4*)(W1 + idx));
            float4 bv  = __ldg((const float4*)(b2 + idx));
            ull w0lo = pk2(w0v.x, w0v.y), w0hi = pk2(w0v.z, w0v.w);
            ull w1lo = pk2(w1v.x, w1v.y), w1hi = pk2(w1v.z, w1v.w);
            ull blo  = pk2(bv.x,  bv.y),  bhi  = pk2(bv.z,  bv.w);
#pragma unroll
            for (int e = 0; e < 8; e++) {
                ull z0 = ffma2(ea0p[e], w0lo, blo);
                z0 = ffma2(ea1p[e], w1lo, z0);
                ull z1 = ffma2(ea0p[e], w0hi, bhi);
                z1 = ffma2(ea1p[e], w1hi, z1);
                z0 = relu2(z0);
                z1 = relu2(z1);
                float h;
                if (ii == 0) h = h4[e].x;
                else if (ii == 1) h = h4[e].y;
                else if (ii == 2) h = h4[e].z;
                else h = h4[e].w;
                ull hd = pk2(h, h);
                acc0[e] = ffma2(hd, z0, acc0[e]);
                acc1[e] = ffma2(hd, z1, acc1[e]);
            }
        }
    }

#pragma unroll
    for (int e = 0; e < 8; e++) {
        float v0, v1, v2, v3;
        upk2(acc0[e], v0, v1);
        upk2(acc1[e], v2, v3);
        float* p = agg + didx[e] + o4;
        atomicAdd(p + 0, v0);
        atomicAdd(p + 1, v1);
        atomicAdd(p + 2, v2);
        atomicAdd(p + 3, v3);
    }
}

// ---------------- layer 2 node: h2 = relu(agg/cnt + h1@r2 + c2) ----------------
__global__ void k_l2_node(const float* __restrict__ r2, const float* __restrict__ c2) {
    const int lane = threadIdx.x & 31;
    const int warp = threadIdx.x >> 5;
    const int n = blockIdx.x * 8 + warp;   // 512 blocks * 8 warps = 4096 nodes
    const int o4 = lane << 2;

    ull acc0 = 0ull, acc1 = 0ull;
    const float* hrow = g_h1 + n * 128;
    for (int i = 0; i < 128; i += 4) {
        float4 h4 = *(const float4*)(hrow + i);
        float hv[4] = {h4.x, h4.y, h4.z, h4.w};
#pragma unroll
        for (int ii = 0; ii < 4; ii++) {
            float4 rv = __ldg((const float4*)(r2 + (i + ii) * 128 + o4));
            ull hd = pk2(hv[ii], hv[ii]);
            acc0 = ffma2(hd, pk2(rv.x, rv.y), acc0);
            acc1 = ffma2(hd, pk2(rv.z, rv.w), acc1);
        }
    }
    float inv = 1.f / fmaxf(g_cnt[n], 1.f);
    float v0, v1, v2, v3;
    upk2(acc0, v0, v1);
    upk2(acc1, v2, v3);
    int base = n * 128 + o4;
    g_h2[base + 0] = fmaxf(fmaf(g_agg[base + 0], inv, v0 + __ldg(&c2[o4 + 0])), 0.f);
    g_h2[base + 1] = fmaxf(fmaf(g_agg[base + 1], inv, v1 + __ldg(&c2[o4 + 1])), 0.f);
    g_h2[base + 2] = fmaxf(fmaf(g_agg[base + 2], inv, v2 + __ldg(&c2[o4 + 2])), 0.f);
    g_h2[base + 3] = fmaxf(fmaf(g_agg[base + 3], inv, v3 + __ldg(&c2[o4 + 3])), 0.f);
}

// ---------------- layer 3 edge: 128 -> 2, warp per edge ----------------
__global__ void k_l3_edge(const float* __restrict__ ea,
                          const int* __restrict__ src, const int* __restrict__ dst,
                          const float* __restrict__ w3, const float* __restrict__ b3) {
    const int lane = threadIdx.x & 31;
    const int warp = threadIdx.x >> 5;
    const int e = blockIdx.x * 8 + warp;   // 2048 blocks * 8 warps = 16384 edges
    if (e >= E_EDGES) return;
    float a0 = __ldg(&ea[2 * e]);
    float a1 = __ldg(&ea[2 * e + 1]);
    int s = __ldg(&src[e]);
    float s0 = 0.f, s1 = 0.f;
    for (int i = lane; i < 128; i += 32) {
        float h = g_h2[s * 128 + i];
        int idx = 2 * i;
        float z0 = fmaf(a1, __ldg(&w3[256 + idx]),     fmaf(a0, __ldg(&w3[idx]),     __ldg(&b3[idx])));
        float z1 = fmaf(a1, __ldg(&w3[256 + idx + 1]), fmaf(a0, __ldg(&w3[idx + 1]), __ldg(&b3[idx + 1])));
        s0 = fmaf(h, fmaxf(z0, 0.f), s0);
        s1 = fmaf(h, fmaxf(z1, 0.f), s1);
    }
#pragma unroll
    for (int off = 16; off > 0; off >>= 1) {
        s0 += __shfl_down_sync(0xFFFFFFFFu, s0, off);
        s1 += __shfl_down_sync(0xFFFFFFFFu, s1, off);
    }
    if (lane == 0) {
        int d = __ldg(&dst[e]);
        atomicAdd(&g_agg3[2 * d + 0], s0);
        atomicAdd(&g_agg3[2 * d + 1], s1);
    }
}

// ---------------- layer 3 node: out = agg/cnt + h2@r3 + c3 ----------------
__global__ void k_l3_node(const float* __restrict__ r3, const float* __restrict__ c3,
                          float* __restrict__ out) {
    const int lane = threadIdx.x & 31;
    const int warp = threadIdx.x >> 5;
    const int n = blockIdx.x * 8 + warp;   // 512 blocks * 8 warps = 4096 nodes
    float s0 = 0.f, s1 = 0.f;
    for (int i = lane; i < 128; i += 32) {
        float h = g_h2[n * 128 + i];
        s0 = fmaf(h, __ldg(&r3[2 * i + 0]), s0);
        s1 = fmaf(h, __ldg(&r3[2 * i + 1]), s1);
    }
#pragma unroll
    for (int off = 16; off > 0; off >>= 1) {
        s0 += __shfl_down_sync(0xFFFFFFFFu, s0, off);
        s1 += __shfl_down_sync(0xFFFFFFFFu, s1, off);
    }
    if (lane == 0) {
        float inv = 1.f / fmaxf(g_cnt[n], 1.f);
        out[2 * n + 0] = fmaf(g_agg3[2 * n + 0], inv, s0 + __ldg(&c3[0]));
        out[2 * n + 1] = fmaf(g_agg3[2 * n + 1], inv, s1 + __ldg(&c3[1]));
    }
}

// ---------------- launch ----------------
extern "C" void kernel_launch(void* const* d_in, const int* in_sizes, int n_in,
                              void* d_out, int out_size) {
    const float* x   = (const float*)d_in[0];
    const float* ea  = (const float*)d_in[1];
    const int*   src = (const int*)d_in[2];
    const int*   dst = (const int*)d_in[3];
    const float* w1  = (const float*)d_in[4];
    const float* b1  = (const float*)d_in[5];
    const float* r1  = (const float*)d_in[6];
    const float* c1  = (const float*)d_in[7];
    const float* w2  = (const float*)d_in[8];
    const float* b2  = (const float*)d_in[9];
    const float* r2  = (const float*)d_in[10];
    const float* c2  = (const float*)d_in[11];
    const float* w3  = (const float*)d_in[12];
    const float* b3  = (const float*)d_in[13];
    const float* r3  = (const float*)d_in[14];
    const float* c3  = (const float*)d_in[15];
    float* out = (float*)d_out;

    float* aggp;
    cudaGetSymbolAddress((void**)&aggp, g_agg);
    float* h1p;
    cudaGetSymbolAddress((void**)&h1p, g_h1);

    k_init<<<512, 256>>>();
    k_cnt<<<E_EDGES / 256, 256>>>(dst);
    k_l1_edge<<<(E_EDGES * 128) / 256, 256>>>(x, ea, src, dst, w1, b1);
    k_l1_node<<<(N_NODES * 128) / 256, 256>>>(x, r1, c1);
    k_l2_edge<<<256, 256>>>(h1p, ea, src, dst, w2, b2, aggp);
    k_l2_node<<<N_NODES / 8, 256>>>(r2, c2);
    k_l3_edge<<<E_EDGES / 8, 256>>>(ea, src, dst, w3, b3);   // 2048 blocks
    k_l3_node<<<N_NODES / 8, 256>>>(r3, c3, out);
}

// round 3
// speedup vs baseline: 1.1938x; 1.1938x over previous
#include <cuda_runtime.h>

#define N_NODES 4096
#define E_EDGES 16384
#define HID 128

typedef unsigned long long ull;

// ---------------- scratch (device globals; zero-initialized at module load).
// Every kernel re-zeroes the scratch it consumed, so each graph replay starts
// from the same (zeroed) state: deterministic.
__device__ __align__(16) float g_h1[N_NODES * HID];
__device__ __align__(16) float g_h2[N_NODES * HID];
__device__ __align__(16) float g_agg[N_NODES * HID];
__device__ __align__(16) float g_agg3[N_NODES * 2];
__device__ float g_cnt[N_NODES];

// ---------------- packed fp32x2 helpers (sm_100+) ----------------
__device__ __forceinline__ ull pk2(float lo, float hi) {
    ull r; asm("mov.b64 %0, {%1, %2};" : "=l"(r) : "f"(lo), "f"(hi)); return r;
}
__device__ __forceinline__ void upk2(ull v, float &lo, float &hi) {
    asm("mov.b64 {%0, %1}, %2;" : "=f"(lo), "=f"(hi) : "l"(v));
}
__device__ __forceinline__ ull ffma2(ull a, ull b, ull c) {
    ull r; asm("fma.rn.f32x2 %0, %1, %2, %3;" : "=l"(r) : "l"(a), "l"(b), "l"(c)); return r;
}
// relu(a0*w0 + a1*w1 + b) on a packed pair, single asm block.
__device__ __forceinline__ ull genrelu(ull a0, ull w0, ull a1, ull w1, ull b) {
    ull r;
    asm("{\n\t"
        ".reg .b64 z;\n\t"
        ".reg .f32 lo, hi;\n\t"
        "fma.rn.f32x2 z, %1, %2, %5;\n\t"
        "fma.rn.f32x2 z, %3, %4, z;\n\t"
        "mov.b64 {lo, hi}, z;\n\t"
        "max.f32 lo, lo, 0f00000000;\n\t"
        "max.f32 hi, hi, 0f00000000;\n\t"
        "mov.b64 %0, {lo, hi};\n\t"
        "}"
        : "=l"(r) : "l"(a0), "l"(w0), "l"(a1), "l"(w1), "l"(b));
    return r;
}

// ---------------- in-degree counts ----------------
__global__ void k_cnt(const int* __restrict__ dst) {
    int e = blockIdx.x * blockDim.x + threadIdx.x;
    if (e < E_EDGES) atomicAdd(&g_cnt[dst[e]], 1.f);
}

// ---------------- layer 1 edge: IN=4 -> 128. 4 channels / thread ----------------
__global__ void k_l1_edge(const float* __restrict__ x, const float* __restrict__ ea,
                          const int* __restrict__ src, const int* __restrict__ dst,
                          const float* __restrict__ w1, const float* __restrict__ b1) {
    int t = blockIdx.x * blockDim.x + threadIdx.x;   // E*32 threads
    int e = t >> 5;
    int o4 = (t & 31) << 2;
    float2 a = __ldg((const float2*)(ea + 2 * e));
    int s = __ldg(&src[e]);
    float4 xs = __ldg((const float4*)(x + 4 * s));
    float xv[4] = {xs.x, xs.y, xs.z, xs.w};
    float4 acc = make_float4(0.f, 0.f, 0.f, 0.f);
    const float* W0 = w1;
    const float* W1 = w1 + 512;
#pragma unroll
    for (int i = 0; i < 4; i++) {
        int idx = i * 128 + o4;
        float4 w0v = __ldg((const float4*)(W0 + idx));
        float4 w1v = __ldg((const float4*)(W1 + idx));
        float4 bv  = __ldg((const float4*)(b1 + idx));
        acc.x = fmaf(xv[i], fmaxf(fmaf(a.y, w1v.x, fmaf(a.x, w0v.x, bv.x)), 0.f), acc.x);
        acc.y = fmaf(xv[i], fmaxf(fmaf(a.y, w1v.y, fmaf(a.x, w0v.y, bv.y)), 0.f), acc.y);
        acc.z = fmaf(xv[i], fmaxf(fmaf(a.y, w1v.z, fmaf(a.x, w0v.z, bv.z)), 0.f), acc.z);
        acc.w = fmaf(xv[i], fmaxf(fmaf(a.y, w1v.w, fmaf(a.x, w0v.w, bv.w)), 0.f), acc.w);
    }
    atomicAdd((float4*)(g_agg + __ldg(&dst[e]) * 128 + o4), acc);
}

// ---------------- layer 1 node: h1 = relu(agg/cnt + x@r1 + c1); re-zero agg ----------------
__global__ void k_l1_node(const float* __restrict__ x, const float* __restrict__ r1,
                          const float* __restrict__ c1) {
    int t = blockIdx.x * blockDim.x + threadIdx.x;   // N*32 threads
    int n = t >> 5;
    int o4 = (t & 31) << 2;
    int base = n * 128 + o4;
    float inv = 1.f / fmaxf(g_cnt[n], 1.f);
    float4 xs = __ldg((const float4*)(x + 4 * n));
    float xv[4] = {xs.x, xs.y, xs.z, xs.w};
    float4 ag = *(const float4*)(g_agg + base);
    float4 root = make_float4(0.f, 0.f, 0.f, 0.f);
#pragma unroll
    for (int i = 0; i < 4; i++) {
        float4 rv = __ldg((const float4*)(r1 + i * 128 + o4));
        root.x = fmaf(xv[i], rv.x, root.x);
        root.y = fmaf(xv[i], rv.y, root.y);
        root.z = fmaf(xv[i], rv.z, root.z);
        root.w = fmaf(xv[i], rv.w, root.w);
    }
    float4 cv = __ldg((const float4*)(c1 + o4));
    float4 h;
    h.x = fmaxf(fmaf(ag.x, inv, root.x + cv.x), 0.f);
    h.y = fmaxf(fmaf(ag.y, inv, root.y + cv.y), 0.f);
    h.z = fmaxf(fmaf(ag.z, inv, root.z + cv.z), 0.f);
    h.w = fmaxf(fmaf(ag.w, inv, root.w + cv.w), 0.f);
    *(float4*)(g_h1 + base) = h;
    *(float4*)(g_agg + base) = make_float4(0.f, 0.f, 0.f, 0.f);   // ready for layer 2
}

// ---------------- layer 2 edge: THE hot kernel ----------------
// warp = 8 edges; lane = 4 consecutive output channels (2 f32x2 pairs).
// W loaded as packed ulonglong2 (no pack MOVs). float4 atomics at the end.
__global__ void __launch_bounds__(256) k_l2_edge(
        const float* __restrict__ h1, const float* __restrict__ ea,
        const int* __restrict__ src, const int* __restrict__ dst,
        const float* __restrict__ w2, const float* __restrict__ b2,
        float* __restrict__ agg) {
    const int lane = threadIdx.x & 31;
    const int warp = threadIdx.x >> 5;
    const int ebase = (blockIdx.x * 8 + warp) * 8;   // 256 blocks * 8 warps * 8 edges = 16384

    const ull* W0u = (const ull*)w2;            // [128][64] packed pairs
    const ull* W1u = (const ull*)(w2 + 16384);
    const ull* Bu  = (const ull*)b2;

    ull ea0p[8], ea1p[8];
    int sidx[8];
#pragma unroll
    for (int e = 0; e < 8; e++) {
        float2 a = __ldg((const float2*)(ea + 2 * (ebase + e)));
        ea0p[e] = pk2(a.x, a.x);
        ea1p[e] = pk2(a.y, a.y);
        sidx[e] = __ldg(&src[ebase + e]) * 128;
    }

    ull acc0[8], acc1[8];
#pragma unroll
    for (int e = 0; e < 8; e++) { acc0[e] = 0ull; acc1[e] = 0ull; }

    const int l2 = lane << 1;   // ull column index: 2 pairs per lane

    for (int i4 = 0; i4 < 128; i4 += 4) {
        float4 h4[8];
#pragma unroll
        for (int e = 0; e < 8; e++)
            h4[e] = __ldg((const float4*)(h1 + sidx[e] + i4));
#pragma unroll
        for (int ii = 0; ii < 4; ii++) {
            int idx = (i4 + ii) * 64 + l2;
            ulonglong2 w0 = __ldg((const ulonglong2*)(W0u + idx));
            ulonglong2 w1 = __ldg((const ulonglong2*)(W1u + idx));
            ulonglong2 bv = __ldg((const ulonglong2*)(Bu + idx));
#pragma unroll
            for (int e = 0; e < 8; e++) {
                ull z0 = genrelu(ea0p[e], w0.x, ea1p[e], w1.x, bv.x);
                ull z1 = genrelu(ea0p[e], w0.y, ea1p[e], w1.y, bv.y);
                float h;
                if (ii == 0) h = h4[e].x;
                else if (ii == 1) h = h4[e].y;
                else if (ii == 2) h = h4[e].z;
                else h = h4[e].w;
                ull hd = pk2(h, h);
                acc0[e] = ffma2(hd, z0, acc0[e]);
                acc1[e] = ffma2(hd, z1, acc1[e]);
            }
        }
    }

    const int o4 = lane << 2;
#pragma unroll
    for (int e = 0; e < 8; e++) {
        float4 v;
        upk2(acc0[e], v.x, v.y);
        upk2(acc1[e], v.z, v.w);
        int d = __ldg(&dst[ebase + e]);
        atomicAdd((float4*)(agg + d * 128 + o4), v);
    }
}

// ---------------- layer 2 node: h2 = relu(agg/cnt + h1@r2 + c2); re-zero agg ----------------
__global__ void k_l2_node(const float* __restrict__ r2, const float* __restrict__ c2) {
    const int lane = threadIdx.x & 31;
    const int warp = threadIdx.x >> 5;
    const int n = blockIdx.x * 8 + warp;   // 512 blocks * 8 warps = 4096 nodes
    const int o4 = lane << 2;

    ull acc0 = 0ull, acc1 = 0ull;
    const float* hrow = g_h1 + n * 128;
    const ull* R2u = (const ull*)r2;
    for (int i = 0; i < 128; i += 4) {
        float4 h4 = *(const float4*)(hrow + i);
        float hv[4] = {h4.x, h4.y, h4.z, h4.w};
#pragma unroll
        for (int ii = 0; ii < 4; ii++) {
            ulonglong2 rv = __ldg((const ulonglong2*)(R2u + (i + ii) * 64 + 2 * lane));
            ull hd = pk2(hv[ii], hv[ii]);
            acc0 = ffma2(hd, rv.x, acc0);
            acc1 = ffma2(hd, rv.y, acc1);
        }
    }
    float inv = 1.f / fmaxf(g_cnt[n], 1.f);
    float v0, v1, v2, v3;
    upk2(acc0, v0, v1);
    upk2(acc1, v2, v3);
    int base = n * 128 + o4;
    float4 ag = *(const float4*)(g_agg + base);
    float4 cv = __ldg((const float4*)(c2 + o4));
    float4 h;
    h.x = fmaxf(fmaf(ag.x, inv, v0 + cv.x), 0.f);
    h.y = fmaxf(fmaf(ag.y, inv, v1 + cv.y), 0.f);
    h.z = fmaxf(fmaf(ag.z, inv, v2 + cv.z), 0.f);
    h.w = fmaxf(fmaf(ag.w, inv, v3 + cv.w), 0.f);
    *(float4*)(g_h2 + base) = h;
    *(float4*)(g_agg + base) = make_float4(0.f, 0.f, 0.f, 0.f);   // clean for next replay
}

// ---------------- layer 3 edge: 128 -> 2, warp per edge ----------------
__global__ void k_l3_edge(const float* __restrict__ ea,
                          const int* __restrict__ src, const int* __restrict__ dst,
                          const float* __restrict__ w3, const float* __restrict__ b3) {
    const int lane = threadIdx.x & 31;
    const int warp = threadIdx.x >> 5;
    const int e = blockIdx.x * 8 + warp;   // 2048 blocks * 8 warps = 16384 edges
    float2 a = __ldg((const float2*)(ea + 2 * e));
    int s = __ldg(&src[e]);
    float s0 = 0.f, s1 = 0.f;
#pragma unroll
    for (int rep = 0; rep < 4; rep++) {
        int i = rep * 32 + lane;
        float h = g_h2[s * 128 + i];
        int idx = 2 * i;
        float z0 = fmaf(a.y, __ldg(&w3[256 + idx]),     fmaf(a.x, __ldg(&w3[idx]),     __ldg(&b3[idx])));
        float z1 = fmaf(a.y, __ldg(&w3[256 + idx + 1]), fmaf(a.x, __ldg(&w3[idx + 1]), __ldg(&b3[idx + 1])));
        s0 = fmaf(h, fmaxf(z0, 0.f), s0);
        s1 = fmaf(h, fmaxf(z1, 0.f), s1);
    }
#pragma unroll
    for (int off = 16; off > 0; off >>= 1) {
        s0 += __shfl_down_sync(0xFFFFFFFFu, s0, off);
        s1 += __shfl_down_sync(0xFFFFFFFFu, s1, off);
    }
    if (lane == 0) {
        int d = __ldg(&dst[e]);
        atomicAdd(&g_agg3[2 * d + 0], s0);
        atomicAdd(&g_agg3[2 * d + 1], s1);
    }
}

// ---------------- layer 3 node: out = agg/cnt + h2@r3 + c3; cleanup scratch ----------------
__global__ void k_l3_node(const float* __restrict__ r3, const float* __restrict__ c3,
                          float* __restrict__ out) {
    const int lane = threadIdx.x & 31;
    const int warp = threadIdx.x >> 5;
    const int n = blockIdx.x * 8 + warp;   // 512 blocks * 8 warps = 4096 nodes
    float s0 = 0.f, s1 = 0.f;
#pragma unroll
    for (int rep = 0; rep < 4; rep++) {
        int i = rep * 32 + lane;
        float h = g_h2[n * 128 + i];
        s0 = fmaf(h, __ldg(&r3[2 * i + 0]), s0);
        s1 = fmaf(h, __ldg(&r3[2 * i + 1]), s1);
    }
#pragma unroll
    for (int off = 16; off > 0; off >>= 1) {
        s0 += __shfl_down_sync(0xFFFFFFFFu, s0, off);
        s1 += __shfl_down_sync(0xFFFFFFFFu, s1, off);
    }
    if (lane == 0) {
        float inv = 1.f / fmaxf(g_cnt[n], 1.f);
        out[2 * n + 0] = fmaf(g_agg3[2 * n + 0], inv, s0 + __ldg(&c3[0]));
        out[2 * n + 1] = fmaf(g_agg3[2 * n + 1], inv, s1 + __ldg(&c3[1]));
        // cleanup for next replay
        g_agg3[2 * n + 0] = 0.f;
        g_agg3[2 * n + 1] = 0.f;
        g_cnt[n] = 0.f;
    }
}

// ---------------- launch ----------------
extern "C" void kernel_launch(void* const* d_in, const int* in_sizes, int n_in,
                              void* d_out, int out_size) {
    const float* x   = (const float*)d_in[0];
    const float* ea  = (const float*)d_in[1];
    const int*   src = (const int*)d_in[2];
    const int*   dst = (const int*)d_in[3];
    const float* w1  = (const float*)d_in[4];
    const float* b1  = (const float*)d_in[5];
    const float* r1  = (const float*)d_in[6];
    const float* c1  = (const float*)d_in[7];
    const float* w2  = (const float*)d_in[8];
    const float* b2  = (const float*)d_in[9];
    const float* r2  = (const float*)d_in[10];
    const float* c2  = (const float*)d_in[11];
    const float* w3  = (const float*)d_in[12];
    const float* b3  = (const float*)d_in[13];
    const float* r3  = (const float*)d_in[14];
    const float* c3  = (const float*)d_in[15];
    float* out = (float*)d_out;

    float* aggp;
    cudaGetSymbolAddress((void**)&aggp, g_agg);
    float* h1p;
    cudaGetSymbolAddress((void**)&h1p, g_h1);

    k_cnt<<<E_EDGES / 256, 256>>>(dst);                       // 1
    k_l1_edge<<<(E_EDGES * 32) / 256, 256>>>(x, ea, src, dst, w1, b1);  // 2
    k_l1_node<<<(N_NODES * 32) / 256, 256>>>(x, r1, c1);      // 3
    k_l2_edge<<<256, 256>>>(h1p, ea, src, dst, w2, b2, aggp); // 4  (capture target)
    k_l2_node<<<N_NODES / 8, 256>>>(r2, c2);                  // 5
    k_l3_edge<<<E_EDGES / 8, 256>>>(ea, src, dst, w3, b3);    // 6
    k_l3_node<<<N_NODES / 8, 256>>>(r3, c3, out);             // 7
}

// round 4
// speedup vs baseline: 1.3302x; 1.1143x over previous
#include <cuda_runtime.h>

#define N_NODES 4096
#define E_EDGES 16384
#define HID 128

typedef unsigned long long ull;

// ---------------- scratch (device globals; zero-initialized at module load).
// Every kernel re-zeroes the scratch it consumed, so each graph replay starts
// from the same (zeroed) state: deterministic.
__device__ __align__(16) float g_h1[N_NODES * HID];
__device__ __align__(16) float g_h2[N_NODES * HID];
__device__ __align__(16) float g_agg[N_NODES * HID];
__device__ __align__(16) float g_agg3[N_NODES * 2];
__device__ float g_cnt[N_NODES];

// ---------------- packed fp32x2 helpers (sm_100+) ----------------
__device__ __forceinline__ ull pk2(float lo, float hi) {
    ull r; asm("mov.b64 %0, {%1, %2};" : "=l"(r) : "f"(lo), "f"(hi)); return r;
}
__device__ __forceinline__ void upk2(ull v, float &lo, float &hi) {
    asm("mov.b64 {%0, %1}, %2;" : "=f"(lo), "=f"(hi) : "l"(v));
}
__device__ __forceinline__ ull ffma2(ull a, ull b, ull c) {
    ull r; asm("fma.rn.f32x2 %0, %1, %2, %3;" : "=l"(r) : "l"(a), "l"(b), "l"(c)); return r;
}
// relu(a0*w0 + a1*w1 + b) on a packed pair, single asm block.
__device__ __forceinline__ ull genrelu(ull a0, ull w0, ull a1, ull w1, ull b) {
    ull r;
    asm("{\n\t"
        ".reg .b64 z;\n\t"
        ".reg .f32 lo, hi;\n\t"
        "fma.rn.f32x2 z, %1, %2, %5;\n\t"
        "fma.rn.f32x2 z, %3, %4, z;\n\t"
        "mov.b64 {lo, hi}, z;\n\t"
        "max.f32 lo, lo, 0f00000000;\n\t"
        "max.f32 hi, hi, 0f00000000;\n\t"
        "mov.b64 %0, {lo, hi};\n\t"
        "}"
        : "=l"(r) : "l"(a0), "l"(w0), "l"(a1), "l"(w1), "l"(b));
    return r;
}

// ---------------- in-degree counts ----------------
__global__ void k_cnt(const int* __restrict__ dst) {
    int e = blockIdx.x * blockDim.x + threadIdx.x;
    if (e < E_EDGES) atomicAdd(&g_cnt[dst[e]], 1.f);
}

// ---------------- layer 1 edge: IN=4 -> 128. 4 channels / thread ----------------
__global__ void k_l1_edge(const float* __restrict__ x, const float* __restrict__ ea,
                          const int* __restrict__ src, const int* __restrict__ dst,
                          const float* __restrict__ w1, const float* __restrict__ b1) {
    int t = blockIdx.x * blockDim.x + threadIdx.x;   // E*32 threads
    int e = t >> 5;
    int o4 = (t & 31) << 2;
    float2 a = __ldg((const float2*)(ea + 2 * e));
    int s = __ldg(&src[e]);
    float4 xs = __ldg((const float4*)(x + 4 * s));
    float xv[4] = {xs.x, xs.y, xs.z, xs.w};
    float4 acc = make_float4(0.f, 0.f, 0.f, 0.f);
    const float* W0 = w1;
    const float* W1 = w1 + 512;
#pragma unroll
    for (int i = 0; i < 4; i++) {
        int idx = i * 128 + o4;
        float4 w0v = __ldg((const float4*)(W0 + idx));
        float4 w1v = __ldg((const float4*)(W1 + idx));
        float4 bv  = __ldg((const float4*)(b1 + idx));
        acc.x = fmaf(xv[i], fmaxf(fmaf(a.y, w1v.x, fmaf(a.x, w0v.x, bv.x)), 0.f), acc.x);
        acc.y = fmaf(xv[i], fmaxf(fmaf(a.y, w1v.y, fmaf(a.x, w0v.y, bv.y)), 0.f), acc.y);
        acc.z = fmaf(xv[i], fmaxf(fmaf(a.y, w1v.z, fmaf(a.x, w0v.z, bv.z)), 0.f), acc.z);
        acc.w = fmaf(xv[i], fmaxf(fmaf(a.y, w1v.w, fmaf(a.x, w0v.w, bv.w)), 0.f), acc.w);
    }
    atomicAdd((float4*)(g_agg + __ldg(&dst[e]) * 128 + o4), acc);
}

// ---------------- layer 1 node: h1 = relu(agg/cnt + x@r1 + c1); re-zero agg ----------------
__global__ void k_l1_node(const float* __restrict__ x, const float* __restrict__ r1,
                          const float* __restrict__ c1) {
    int t = blockIdx.x * blockDim.x + threadIdx.x;   // N*32 threads
    int n = t >> 5;
    int o4 = (t & 31) << 2;
    int base = n * 128 + o4;
    float inv = 1.f / fmaxf(g_cnt[n], 1.f);
    float4 xs = __ldg((const float4*)(x + 4 * n));
    float xv[4] = {xs.x, xs.y, xs.z, xs.w};
    float4 ag = *(const float4*)(g_agg + base);
    float4 root = make_float4(0.f, 0.f, 0.f, 0.f);
#pragma unroll
    for (int i = 0; i < 4; i++) {
        float4 rv = __ldg((const float4*)(r1 + i * 128 + o4));
        root.x = fmaf(xv[i], rv.x, root.x);
        root.y = fmaf(xv[i], rv.y, root.y);
        root.z = fmaf(xv[i], rv.z, root.z);
        root.w = fmaf(xv[i], rv.w, root.w);
    }
    float4 cv = __ldg((const float4*)(c1 + o4));
    float4 h;
    h.x = fmaxf(fmaf(ag.x, inv, root.x + cv.x), 0.f);
    h.y = fmaxf(fmaf(ag.y, inv, root.y + cv.y), 0.f);
    h.z = fmaxf(fmaf(ag.z, inv, root.z + cv.z), 0.f);
    h.w = fmaxf(fmaf(ag.w, inv, root.w + cv.w), 0.f);
    *(float4*)(g_h1 + base) = h;
    *(float4*)(g_agg + base) = make_float4(0.f, 0.f, 0.f, 0.f);   // ready for layer 2
}

// ---------------- layer 2 edge: THE hot kernel ----------------
// warp-job = 4 edges x 64 i-values; lane = 4 output channels (2 f32x2 pairs).
// 8192 warp-jobs over 1024 blocks; 3 blocks/SM (launch_bounds) -> 24 warps/SM.
__global__ void __launch_bounds__(256, 3) k_l2_edge(
        const float* __restrict__ h1, const float* __restrict__ ea,
        const int* __restrict__ src, const int* __restrict__ dst,
        const float* __restrict__ w2, const float* __restrict__ b2,
        float* __restrict__ agg) {
    const int lane = threadIdx.x & 31;
    const int wjob = (blockIdx.x << 3) + (threadIdx.x >> 5);  // 0..8191
    const int grp  = wjob >> 1;          // edge group 0..4095
    const int ebase = grp << 2;          // 4 edges
    const int ibase = (wjob & 1) << 6;   // i in [0,64) or [64,128)

    const ull* W0u = (const ull*)w2;            // [128][64] packed pairs
    const ull* W1u = (const ull*)(w2 + 16384);
    const ull* Bu  = (const ull*)b2;

    ull ea0p[4], ea1p[4];
    int sidx[4];
#pragma unroll
    for (int e = 0; e < 4; e++) {
        float2 a = __ldg((const float2*)(ea + 2 * (ebase + e)));
        ea0p[e] = pk2(a.x, a.x);
        ea1p[e] = pk2(a.y, a.y);
        sidx[e] = __ldg(&src[ebase + e]) * 128;
    }

    ull acc0[4], acc1[4];
#pragma unroll
    for (int e = 0; e < 4; e++) { acc0[e] = 0ull; acc1[e] = 0ull; }

    const int l2 = lane << 1;   // ull column index: 2 pairs per lane

    for (int i4 = ibase; i4 < ibase + 64; i4 += 4) {
        float4 h4[4];
#pragma unroll
        for (int e = 0; e < 4; e++)
            h4[e] = __ldg((const float4*)(h1 + sidx[e] + i4));
#pragma unroll
        for (int ii = 0; ii < 4; ii++) {
            int idx = (i4 + ii) * 64 + l2;
            ulonglong2 w0 = __ldg((const ulonglong2*)(W0u + idx));
            ulonglong2 w1 = __ldg((const ulonglong2*)(W1u + idx));
            ulonglong2 bv = __ldg((const ulonglong2*)(Bu + idx));
#pragma unroll
            for (int e = 0; e < 4; e++) {
                ull z0 = genrelu(ea0p[e], w0.x, ea1p[e], w1.x, bv.x);
                ull z1 = genrelu(ea0p[e], w0.y, ea1p[e], w1.y, bv.y);
                float h;
                if (ii == 0) h = h4[e].x;
                else if (ii == 1) h = h4[e].y;
                else if (ii == 2) h = h4[e].z;
                else h = h4[e].w;
                ull hd = pk2(h, h);
                acc0[e] = ffma2(hd, z0, acc0[e]);
                acc1[e] = ffma2(hd, z1, acc1[e]);
            }
        }
    }

    const int o4 = lane << 2;
#pragma unroll
    for (int e = 0; e < 4; e++) {
        float4 v;
        upk2(acc0[e], v.x, v.y);
        upk2(acc1[e], v.z, v.w);
        int d = __ldg(&dst[ebase + e]);
        atomicAdd((float4*)(agg + d * 128 + o4), v);
    }
}

// ---------------- layer 2 node: h2 = relu(agg/cnt + h1@r2 + c2); re-zero agg ----------------
__global__ void k_l2_node(const float* __restrict__ r2, const float* __restrict__ c2) {
    const int lane = threadIdx.x & 31;
    const int warp = threadIdx.x >> 5;
    const int n = blockIdx.x * 8 + warp;   // 512 blocks * 8 warps = 4096 nodes
    const int o4 = lane << 2;

    ull acc0 = 0ull, acc1 = 0ull;
    const float* hrow = g_h1 + n * 128;
    const ull* R2u = (const ull*)r2;
    for (int i = 0; i < 128; i += 4) {
        float4 h4 = *(const float4*)(hrow + i);
        float hv[4] = {h4.x, h4.y, h4.z, h4.w};
#pragma unroll
        for (int ii = 0; ii < 4; ii++) {
            ulonglong2 rv = __ldg((const ulonglong2*)(R2u + (i + ii) * 64 + 2 * lane));
            ull hd = pk2(hv[ii], hv[ii]);
            acc0 = ffma2(hd, rv.x, acc0);
            acc1 = ffma2(hd, rv.y, acc1);
        }
    }
    float inv = 1.f / fmaxf(g_cnt[n], 1.f);
    float v0, v1, v2, v3;
    upk2(acc0, v0, v1);
    upk2(acc1, v2, v3);
    int base = n * 128 + o4;
    float4 ag = *(const float4*)(g_agg + base);
    float4 cv = __ldg((const float4*)(c2 + o4));
    float4 h;
    h.x = fmaxf(fmaf(ag.x, inv, v0 + cv.x), 0.f);
    h.y = fmaxf(fmaf(ag.y, inv, v1 + cv.y), 0.f);
    h.z = fmaxf(fmaf(ag.z, inv, v2 + cv.z), 0.f);
    h.w = fmaxf(fmaf(ag.w, inv, v3 + cv.w), 0.f);
    *(float4*)(g_h2 + base) = h;
    *(float4*)(g_agg + base) = make_float4(0.f, 0.f, 0.f, 0.f);   // clean for next replay
}

// ---------------- layer 3 edge: 128 -> 2, warp per edge ----------------
__global__ void k_l3_edge(const float* __restrict__ ea,
                          const int* __restrict__ src, const int* __restrict__ dst,
                          const float* __restrict__ w3, const float* __restrict__ b3) {
    const int lane = threadIdx.x & 31;
    const int warp = threadIdx.x >> 5;
    const int e = blockIdx.x * 8 + warp;   // 2048 blocks * 8 warps = 16384 edges
    float2 a = __ldg((const float2*)(ea + 2 * e));
    int s = __ldg(&src[e]);
    float s0 = 0.f, s1 = 0.f;
#pragma unroll
    for (int rep = 0; rep < 4; rep++) {
        int i = rep * 32 + lane;
        float h = g_h2[s * 128 + i];
        int idx = 2 * i;
        float z0 = fmaf(a.y, __ldg(&w3[256 + idx]),     fmaf(a.x, __ldg(&w3[idx]),     __ldg(&b3[idx])));
        float z1 = fmaf(a.y, __ldg(&w3[256 + idx + 1]), fmaf(a.x, __ldg(&w3[idx + 1]), __ldg(&b3[idx + 1])));
        s0 = fmaf(h, fmaxf(z0, 0.f), s0);
        s1 = fmaf(h, fmaxf(z1, 0.f), s1);
    }
#pragma unroll
    for (int off = 16; off > 0; off >>= 1) {
        s0 += __shfl_down_sync(0xFFFFFFFFu, s0, off);
        s1 += __shfl_down_sync(0xFFFFFFFFu, s1, off);
    }
    if (lane == 0) {
        int d = __ldg(&dst[e]);
        atomicAdd(&g_agg3[2 * d + 0], s0);
        atomicAdd(&g_agg3[2 * d + 1], s1);
    }
}

// ---------------- layer 3 node: out = agg/cnt + h2@r3 + c3; cleanup scratch ----------------
__global__ void k_l3_node(const float* __restrict__ r3, const float* __restrict__ c3,
                          float* __restrict__ out) {
    const int lane = threadIdx.x & 31;
    const int warp = threadIdx.x >> 5;
    const int n = blockIdx.x * 8 + warp;   // 512 blocks * 8 warps = 4096 nodes
    float s0 = 0.f, s1 = 0.f;
#pragma unroll
    for (int rep = 0; rep < 4; rep++) {
        int i = rep * 32 + lane;
        float h = g_h2[n * 128 + i];
        s0 = fmaf(h, __ldg(&r3[2 * i + 0]), s0);
        s1 = fmaf(h, __ldg(&r3[2 * i + 1]), s1);
    }
#pragma unroll
    for (int off = 16; off > 0; off >>= 1) {
        s0 += __shfl_down_sync(0xFFFFFFFFu, s0, off);
        s1 += __shfl_down_sync(0xFFFFFFFFu, s1, off);
    }
    if (lane == 0) {
        float inv = 1.f / fmaxf(g_cnt[n], 1.f);
        out[2 * n + 0] = fmaf(g_agg3[2 * n + 0], inv, s0 + __ldg(&c3[0]));
        out[2 * n + 1] = fmaf(g_agg3[2 * n + 1], inv, s1 + __ldg(&c3[1]));
        // cleanup for next replay
        g_agg3[2 * n + 0] = 0.f;
        g_agg3[2 * n + 1] = 0.f;
        g_cnt[n] = 0.f;
    }
}

// ---------------- launch ----------------
extern "C" void kernel_launch(void* const* d_in, const int* in_sizes, int n_in,
                              void* d_out, int out_size) {
    const float* x   = (const float*)d_in[0];
    const float* ea  = (const float*)d_in[1];
    const int*   src = (const int*)d_in[2];
    const int*   dst = (const int*)d_in[3];
    const float* w1  = (const float*)d_in[4];
    const float* b1  = (const float*)d_in[5];
    const float* r1  = (const float*)d_in[6];
    const float* c1  = (const float*)d_in[7];
    const float* w2  = (const float*)d_in[8];
    const float* b2  = (const float*)d_in[9];
    const float* r2  = (const float*)d_in[10];
    const float* c2  = (const float*)d_in[11];
    const float* w3  = (const float*)d_in[12];
    const float* b3  = (const float*)d_in[13];
    const float* r3  = (const float*)d_in[14];
    const float* c3  = (const float*)d_in[15];
    float* out = (float*)d_out;

    float* aggp;
    cudaGetSymbolAddress((void**)&aggp, g_agg);
    float* h1p;
    cudaGetSymbolAddress((void**)&h1p, g_h1);

    k_cnt<<<E_EDGES / 256, 256>>>(dst);                        // 1
    k_l1_edge<<<(E_EDGES * 32) / 256, 256>>>(x, ea, src, dst, w1, b1);  // 2
    k_l1_node<<<(N_NODES * 32) / 256, 256>>>(x, r1, c1);       // 3
    k_l2_edge<<<1024, 256>>>(h1p, ea, src, dst, w2, b2, aggp); // 4  (capture target)
    k_l2_node<<<N_NODES / 8, 256>>>(r2, c2);                   // 5
    k_l3_edge<<<E_EDGES / 8, 256>>>(ea, src, dst, w3, b3);     // 6
    k_l3_node<<<N_NODES / 8, 256>>>(r3, c3, out);              // 7
}